// round 3
// baseline (speedup 1.0000x reference)
#include <cuda_runtime.h>

// ContourIntegrationLayer: 3x3 depthwise conv (center tap zeroed) + residual.
// x: [B=32, H=56, W=56, C=256] f32 NHWC.  kernel: [3,3,256] f32.
// out[b,h,w,c] = sum_{ky,kx != center} k[ky,kx,c] * x[b,h+ky-1,w+kx-1,c] + x[b,h,w,c]
//
// Strategy: HBM-bound. float4 over channels (C4=64 float4 per pixel),
// register-block RH=4 output rows per thread so each of the 6 needed input
// rows is loaded exactly once (4.5 loads/output vs 9 naive). Adjacent-w
// threads within a block overlap 2/3 of their loads -> L1 hits.

#define BH 56
#define BW 56
#define NC4 64          // 256 channels / 4
#define RH 4            // output rows per thread
#define WPB 4           // w positions per block (blockDim.y)

__device__ __forceinline__ float4 f4zero() { return make_float4(0.f, 0.f, 0.f, 0.f); }

__device__ __forceinline__ void fma4(float4& a, const float4 k, const float4 v) {
    a.x = fmaf(k.x, v.x, a.x);
    a.y = fmaf(k.y, v.y, a.y);
    a.z = fmaf(k.z, v.z, a.z);
    a.w = fmaf(k.w, v.w, a.w);
}

__device__ __forceinline__ void add4(float4& a, const float4 v) {
    a.x += v.x; a.y += v.y; a.z += v.z; a.w += v.w;
}

__global__ __launch_bounds__(NC4 * WPB)
void contour_kernel(const float4* __restrict__ x,
                    const float4* __restrict__ kern,
                    float4* __restrict__ out) {
    const int c4 = threadIdx.x;                          // 0..63
    const int w  = blockIdx.x * WPB + threadIdx.y;       // 0..55
    const int h0 = blockIdx.y * RH;                      // 0,4,...,52
    const int b  = blockIdx.z;                           // 0..31

    // Load the 9 per-channel taps (float4 of channels). Center tap zeroed.
    float4 kk[3][3];
#pragma unroll
    for (int ky = 0; ky < 3; ky++)
#pragma unroll
        for (int kx = 0; kx < 3; kx++)
            kk[ky][kx] = __ldg(&kern[(ky * 3 + kx) * NC4 + c4]);
    kk[1][1] = f4zero();

    const int base_b = b * BH * BW * NC4;

    float4 acc[RH];
#pragma unroll
    for (int r = 0; r < RH; r++) acc[r] = f4zero();

#pragma unroll
    for (int j = -1; j <= RH; j++) {           // input row offset within tile
        const int hr = h0 + j;
        const bool hv = (hr >= 0) && (hr < BH);
        const int rowbase = base_b + hr * BW * NC4;

        float4 xm = f4zero(), xc = f4zero(), xp = f4zero();
        if (hv) {
            if (w > 0)       xm = __ldg(&x[rowbase + (w - 1) * NC4 + c4]);
                             xc = __ldg(&x[rowbase +  w      * NC4 + c4]);
            if (w < BW - 1)  xp = __ldg(&x[rowbase + (w + 1) * NC4 + c4]);
        }

#pragma unroll
        for (int dy = 0; dy < 3; dy++) {
            const int r = j + 1 - dy;          // output row index using this input row
            if (r >= 0 && r < RH) {
                fma4(acc[r], kk[dy][0], xm);
                fma4(acc[r], kk[dy][1], xc);   // center tap is zero when dy==1
                fma4(acc[r], kk[dy][2], xp);
                if (dy == 1) add4(acc[r], xc); // residual: x[b, h0+r, w, :]
            }
        }
    }

#pragma unroll
    for (int r = 0; r < RH; r++) {
        out[base_b + (h0 + r) * BW * NC4 + w * NC4 + c4] = acc[r];
    }
}

extern "C" void kernel_launch(void* const* d_in, const int* in_sizes, int n_in,
                              void* d_out, int out_size) {
    const float4* x    = (const float4*)d_in[0];   // [32,56,56,256] f32
    const float4* kern = (const float4*)d_in[1];   // [3,3,256] f32
    float4* out        = (float4*)d_out;

    dim3 block(NC4, WPB);            // 64 x 4 = 256 threads
    dim3 grid(BW / WPB, BH / RH, 32); // (14, 14, 32)
    contour_kernel<<<grid, block>>>(x, kern, out);
}

// round 5
// speedup vs baseline: 1.0911x; 1.0911x over previous
#include <cuda_runtime.h>

// ContourIntegrationLayer: 3x3 depthwise conv (center tap zeroed) + residual.
// x: [B=32, H=56, W=56, C=256] f32 NHWC.  kernel: [3,3,256] f32.
//
// R3 strategy: smem-tiled. Block = 4x4 output pixels x 64 float4 channels.
// Load phase: 6x6x64 float4 halo tile (36 KB) via 9 independent coalesced
// LDG.128 per thread (MLP=9 -> hides DRAM/L2 latency even at 50% occ).
// Compute phase: from smem, one output row at a time (low reg pressure).

#define BH 56
#define BW 56
#define NC4 64          // 256 channels / 4
#define RH 4            // output rows per block tile
#define WPB 4           // output cols per block tile
#define TR (RH + 2)     // input tile rows = 6
#define TC (WPB + 2)    // input tile cols = 6
#define TILE_ELEMS (TR * TC * NC4)   // 2304 float4
#define NTHREADS (NC4 * WPB)         // 256
#define LDS_PER_THREAD (TILE_ELEMS / NTHREADS)  // 9

__device__ __forceinline__ float4 f4zero() { return make_float4(0.f, 0.f, 0.f, 0.f); }

__device__ __forceinline__ void fma4(float4& a, const float4 k, const float4 v) {
    a.x = fmaf(k.x, v.x, a.x);
    a.y = fmaf(k.y, v.y, a.y);
    a.z = fmaf(k.z, v.z, a.z);
    a.w = fmaf(k.w, v.w, a.w);
}

__device__ __forceinline__ void add4(float4& a, const float4 v) {
    a.x += v.x; a.y += v.y; a.z += v.z; a.w += v.w;
}

__global__ __launch_bounds__(NTHREADS)
void contour_kernel(const float4* __restrict__ x,
                    const float4* __restrict__ kern,
                    float4* __restrict__ out) {
    __shared__ float4 tile[TILE_ELEMS];   // 36 KB: [row][col][c4]

    const int tid = threadIdx.x + NC4 * threadIdx.y;   // 0..255
    const int c4  = threadIdx.x;                       // 0..63
    const int ty  = threadIdx.y;                       // 0..3 (output col in tile)
    const int w0  = blockIdx.x * WPB;                  // tile origin w
    const int h0  = blockIdx.y * RH;                   // tile origin h
    const int b   = blockIdx.z;

    const int base_b = b * BH * BW * NC4;

    // ---- Load phase: 9 independent bulk loads, all issued before any wait ----
    float4 ld[LDS_PER_THREAD];
#pragma unroll
    for (int k = 0; k < LDS_PER_THREAD; k++) {
        const int e   = tid + k * NTHREADS;            // 0..2303
        const int row = e / (TC * NC4);                // /384
        const int rem = e - row * (TC * NC4);
        const int col = rem / NC4;
        const int cc  = rem - col * NC4;
        const int hr  = h0 + row - 1;
        const int wc  = w0 + col - 1;
        const bool v  = (hr >= 0) && (hr < BH) && (wc >= 0) && (wc < BW);
        ld[k] = v ? __ldg(&x[base_b + (hr * BW + wc) * NC4 + cc]) : f4zero();
    }

    // Kernel taps while loads are in flight (tiny, L2-resident after first wave)
    float4 kk[3][3];
#pragma unroll
    for (int ky = 0; ky < 3; ky++)
#pragma unroll
        for (int kx = 0; kx < 3; kx++)
            kk[ky][kx] = __ldg(&kern[(ky * 3 + kx) * NC4 + c4]);
    // center tap replaced by +1.0 -> fuses the residual add into the same FMA
    kk[1][1] = make_float4(1.f, 1.f, 1.f, 1.f);

#pragma unroll
    for (int k = 0; k < LDS_PER_THREAD; k++)
        tile[tid + k * NTHREADS] = ld[k];

    __syncthreads();

    // ---- Compute phase: one output row at a time (acc = 4 regs) ----
#pragma unroll
    for (int r = 0; r < RH; r++) {
        float4 acc = f4zero();
#pragma unroll
        for (int dy = 0; dy < 3; dy++) {
#pragma unroll
            for (int dx = 0; dx < 3; dx++) {
                const float4 v = tile[((r + dy) * TC + (ty + dx)) * NC4 + c4];
                fma4(acc, kk[dy][dx], v);   // dy==1,dx==1: tap==1 -> residual
            }
        }
        out[base_b + ((h0 + r) * BW + (w0 + ty)) * NC4 + c4] = acc;
    }
}

extern "C" void kernel_launch(void* const* d_in, const int* in_sizes, int n_in,
                              void* d_out, int out_size) {
    const float4* x    = (const float4*)d_in[0];   // [32,56,56,256] f32
    const float4* kern = (const float4*)d_in[1];   // [3,3,256] f32
    float4* out        = (float4*)d_out;

    dim3 block(NC4, WPB);                 // 64 x 4 = 256 threads
    dim3 grid(BW / WPB, BH / RH, 32);     // (14, 14, 32)
    contour_kernel<<<grid, block>>>(x, kern, out);
}

// round 10
// speedup vs baseline: 1.3613x; 1.2476x over previous
#include <cuda_runtime.h>
#include <cstdint>

// ContourIntegrationLayer: 3x3 depthwise conv (center tap zeroed) + residual.
// x: [B=32, H=56, W=56, C=256] f32 NHWC.  kernel: [3,3,256] f32.
//
// R5 strategy: L1-throughput was the bottleneck (81.6%). Cut L1 ops/output ~2x:
//  - load phase via cp.async (LDGSTS, zero-fill halo) : 9 ops vs 9 LDG + 9 STS
//  - compute phase with tile-row register reuse       : 18 LDS vs 36 LDS
// Residual fused into center tap (= 1.0).

#define BH 56
#define BW 56
#define NC4 64          // 256 channels / 4
#define RH 4            // output rows per block tile
#define WPB 4           // output cols per block tile
#define TR (RH + 2)     // input tile rows = 6
#define TC (WPB + 2)    // input tile cols = 6
#define TILE_ELEMS (TR * TC * NC4)   // 2304 float4
#define NTHREADS (NC4 * WPB)         // 256
#define LDS_PER_THREAD (TILE_ELEMS / NTHREADS)  // 9

__device__ __forceinline__ float4 f4zero() { return make_float4(0.f, 0.f, 0.f, 0.f); }

__device__ __forceinline__ void fma4(float4& a, const float4 k, const float4 v) {
    a.x = fmaf(k.x, v.x, a.x);
    a.y = fmaf(k.y, v.y, a.y);
    a.z = fmaf(k.z, v.z, a.z);
    a.w = fmaf(k.w, v.w, a.w);
}

__device__ __forceinline__ void cp_async16(uint32_t smem_addr, const void* gptr, int src_size) {
    asm volatile("cp.async.cg.shared.global [%0], [%1], 16, %2;\n"
                 :: "r"(smem_addr), "l"(gptr), "r"(src_size) : "memory");
}

__global__ __launch_bounds__(NTHREADS)
void contour_kernel(const float4* __restrict__ x,
                    const float4* __restrict__ kern,
                    float4* __restrict__ out) {
    __shared__ float4 tile[TILE_ELEMS];   // 36 KB: [row][col][c4]

    const int tid = threadIdx.x + NC4 * threadIdx.y;   // 0..255
    const int c4  = threadIdx.x;                       // 0..63
    const int ty  = threadIdx.y;                       // 0..3 (output col in tile)
    const int w0  = blockIdx.x * WPB;                  // tile origin w
    const int h0  = blockIdx.y * RH;                   // tile origin h
    const int b   = blockIdx.z;

    const int base_b = b * BH * BW * NC4;
    const uint32_t smem_base = (uint32_t)__cvta_generic_to_shared(tile);

    // ---- Load phase: 9 LDGSTS per thread, zero-fill for halo OOB ----
#pragma unroll
    for (int k = 0; k < LDS_PER_THREAD; k++) {
        const int e   = tid + k * NTHREADS;            // 0..2303
        const int row = e / (TC * NC4);
        const int rem = e - row * (TC * NC4);
        const int col = rem / NC4;
        const int cc  = rem - col * NC4;
        const int hr  = h0 + row - 1;
        const int wc  = w0 + col - 1;
        const bool v  = (hr >= 0) && (hr < BH) && (wc >= 0) && (wc < BW);
        const int gidx = v ? (base_b + (hr * BW + wc) * NC4 + cc) : 0;
        cp_async16(smem_base + (uint32_t)e * 16u, (const void*)&x[gidx], v ? 16 : 0);
    }
    asm volatile("cp.async.commit_group;\n" ::: "memory");

    // Kernel taps while async loads are in flight. Center tap = 1.0 fuses the
    // residual add into the same FMA chain.
    float4 kk[3][3];
#pragma unroll
    for (int ky = 0; ky < 3; ky++)
#pragma unroll
        for (int kx = 0; kx < 3; kx++)
            kk[ky][kx] = __ldg(&kern[(ky * 3 + kx) * NC4 + c4]);
    kk[1][1] = make_float4(1.f, 1.f, 1.f, 1.f);

    asm volatile("cp.async.wait_group 0;\n" ::: "memory");
    __syncthreads();

    // ---- Compute phase: walk tile rows once, feed all output rows ----
    // Output row r consumes tile rows r..r+2 (tap row dy = jr - r).
    float4 acc[RH];
#pragma unroll
    for (int r = 0; r < RH; r++) acc[r] = f4zero();

#pragma unroll
    for (int jr = 0; jr < TR; jr++) {
        const float4 v0 = tile[(jr * TC + ty    ) * NC4 + c4];
        const float4 v1 = tile[(jr * TC + ty + 1) * NC4 + c4];
        const float4 v2 = tile[(jr * TC + ty + 2) * NC4 + c4];
#pragma unroll
        for (int dy = 0; dy < 3; dy++) {
            const int r = jr - dy;
            if (r >= 0 && r < RH) {
                fma4(acc[r], kk[dy][0], v0);
                fma4(acc[r], kk[dy][1], v1);
                fma4(acc[r], kk[dy][2], v2);
            }
        }
    }

#pragma unroll
    for (int r = 0; r < RH; r++)
        out[base_b + ((h0 + r) * BW + (w0 + ty)) * NC4 + c4] = acc[r];
}

extern "C" void kernel_launch(void* const* d_in, const int* in_sizes, int n_in,
                              void* d_out, int out_size) {
    const float4* x    = (const float4*)d_in[0];   // [32,56,56,256] f32
    const float4* kern = (const float4*)d_in[1];   // [3,3,256] f32
    float4* out        = (float4*)d_out;

    dim3 block(NC4, WPB);                 // 64 x 4 = 256 threads
    dim3 grid(BW / WPB, BH / RH, 32);     // (14, 14, 32)
    contour_kernel<<<grid, block>>>(x, kern, out);
}

// round 11
// speedup vs baseline: 1.3635x; 1.0016x over previous
#include <cuda_runtime.h>
#include <cstdint>

// ContourIntegrationLayer: 3x3 depthwise conv (center tap zeroed) + residual.
// x: [B=32, H=56, W=56, C=256] f32 NHWC.  kernel: [3,3,256] f32.
//
// R10: kernel was instruction-issue-bound (issue=66%, no pipe saturated).
// Convert all conv FMAs to packed fma.rn.f32x2 (FFMA2): 144 FFMA -> 72 FFMA2
// per thread. Data stays in packed u64 (f32x2) form end-to-end, so no
// pack/unpack instructions are added. Load phase: cp.async, MLP=9 (unchanged).

#define BH 56
#define BW 56
#define NC4 64          // 256 channels / 4
#define RH 4            // output rows per block tile
#define WPB 4           // output cols per block tile
#define TR (RH + 2)     // input tile rows = 6
#define TC (WPB + 2)    // input tile cols = 6
#define TILE_ELEMS (TR * TC * NC4)   // 2304 float4
#define NTHREADS (NC4 * WPB)         // 256
#define LDS_PER_THREAD (TILE_ELEMS / NTHREADS)  // 9

__device__ __forceinline__ void cp_async16(uint32_t smem_addr, const void* gptr, int src_size) {
    asm volatile("cp.async.cg.shared.global [%0], [%1], 16, %2;\n"
                 :: "r"(smem_addr), "l"(gptr), "r"(src_size) : "memory");
}

// packed 2-wide f32 FMA: a = k*v + a  (lanes are two adjacent floats)
__device__ __forceinline__ void fma2(unsigned long long& a,
                                     unsigned long long k,
                                     unsigned long long v) {
    asm("fma.rn.f32x2 %0, %1, %2, %0;" : "+l"(a) : "l"(k), "l"(v));
}

__device__ __forceinline__ unsigned long long pack2(float lo, float hi) {
    unsigned long long r;
    asm("mov.b64 %0, {%1, %2};" : "=l"(r) : "f"(lo), "f"(hi));
    return r;
}

__global__ __launch_bounds__(NTHREADS)
void contour_kernel(const float4* __restrict__ x,
                    const float4* __restrict__ kern,
                    float4* __restrict__ out) {
    __shared__ float4 tile[TILE_ELEMS];   // 36 KB: [row][col][c4]

    const int tid = threadIdx.x + NC4 * threadIdx.y;   // 0..255
    const int c4  = threadIdx.x;                       // 0..63
    const int ty  = threadIdx.y;                       // 0..3 (output col in tile)
    const int w0  = blockIdx.x * WPB;                  // tile origin w
    const int h0  = blockIdx.y * RH;                   // tile origin h
    const int b   = blockIdx.z;

    const int base_b = b * BH * BW * NC4;
    const uint32_t smem_base = (uint32_t)__cvta_generic_to_shared(tile);

    // ---- Load phase: 9 LDGSTS per thread, zero-fill for halo OOB ----
#pragma unroll
    for (int k = 0; k < LDS_PER_THREAD; k++) {
        const int e   = tid + k * NTHREADS;            // 0..2303
        const int row = e / (TC * NC4);
        const int rem = e - row * (TC * NC4);
        const int col = rem / NC4;
        const int cc  = rem - col * NC4;
        const int hr  = h0 + row - 1;
        const int wc  = w0 + col - 1;
        const bool v  = (hr >= 0) && (hr < BH) && (wc >= 0) && (wc < BW);
        const int gidx = v ? (base_b + (hr * BW + wc) * NC4 + cc) : 0;
        cp_async16(smem_base + (uint32_t)e * 16u, (const void*)&x[gidx], v ? 16 : 0);
    }
    asm volatile("cp.async.commit_group;\n" ::: "memory");

    // Kernel taps while async loads are in flight; keep as packed f32x2 pairs.
    // Center tap = (1,1) fuses the residual add into the FMA chain.
    unsigned long long kL[3][3], kH[3][3];
#pragma unroll
    for (int ky = 0; ky < 3; ky++)
#pragma unroll
        for (int kx = 0; kx < 3; kx++) {
            const float4 kf = __ldg(&kern[(ky * 3 + kx) * NC4 + c4]);
            kL[ky][kx] = pack2(kf.x, kf.y);
            kH[ky][kx] = pack2(kf.z, kf.w);
        }
    kL[1][1] = pack2(1.f, 1.f);
    kH[1][1] = pack2(1.f, 1.f);

    asm volatile("cp.async.wait_group 0;\n" ::: "memory");
    __syncthreads();

    // ---- Compute phase: walk tile rows once, feed all output rows ----
    unsigned long long accL[RH], accH[RH];
#pragma unroll
    for (int r = 0; r < RH; r++) { accL[r] = 0ull; accH[r] = 0ull; }

    const ulonglong2* tile2 = (const ulonglong2*)tile;

#pragma unroll
    for (int jr = 0; jr < TR; jr++) {
        const ulonglong2 v0 = tile2[(jr * TC + ty    ) * NC4 + c4];
        const ulonglong2 v1 = tile2[(jr * TC + ty + 1) * NC4 + c4];
        const ulonglong2 v2 = tile2[(jr * TC + ty + 2) * NC4 + c4];
#pragma unroll
        for (int dy = 0; dy < 3; dy++) {
            const int r = jr - dy;
            if (r >= 0 && r < RH) {
                fma2(accL[r], kL[dy][0], v0.x);  fma2(accH[r], kH[dy][0], v0.y);
                fma2(accL[r], kL[dy][1], v1.x);  fma2(accH[r], kH[dy][1], v1.y);
                fma2(accL[r], kL[dy][2], v2.x);  fma2(accH[r], kH[dy][2], v2.y);
            }
        }
    }

    ulonglong2* out2 = (ulonglong2*)out;
#pragma unroll
    for (int r = 0; r < RH; r++) {
        ulonglong2 o;
        o.x = accL[r];
        o.y = accH[r];
        out2[base_b + ((h0 + r) * BW + (w0 + ty)) * NC4 + c4] = o;
    }
}

extern "C" void kernel_launch(void* const* d_in, const int* in_sizes, int n_in,
                              void* d_out, int out_size) {
    const float4* x    = (const float4*)d_in[0];   // [32,56,56,256] f32
    const float4* kern = (const float4*)d_in[1];   // [3,3,256] f32
    float4* out        = (float4*)d_out;

    dim3 block(NC4, WPB);                 // 64 x 4 = 256 threads
    dim3 grid(BW / WPB, BH / RH, 32);     // (14, 14, 32)
    contour_kernel<<<grid, block>>>(x, kern, out);
}